// round 11
// baseline (speedup 1.0000x reference)
#include <cuda_runtime.h>
#include <cstdint>

// ============================================================================
// OneHotEncoding — single kernel, zero grid barriers, block-local argmin.
//
// R10 lesson: the per-block UB probe (1024 samples x 128 receivers, redundant
// in all 152 blocks) was ~15% of the original brute force and dominated the
// kernel (~8-10us). A looser UB is nearly free in the stream (per-warp cost of
// extra candidates is ~3 instrs/pt), so: PROBE_N 1024->256, KCAP 5->8.
// Also: AoS smem staging (no div-by-3 index math; stride-3 LDS is conflict-
// free since gcd(3,32)=1) and double-buffered tiles (1 barrier per tile).
//
// Output layout (float32):
//   [0, 4L)            input_tensor: per point (x, y, z, one_hot)
//   [4L, 4L+3B)        closest_points [B,3]
//   [4L+3B, 4L+4B)     min_index as float [B]
//
// Merge key: ~((u64)d2bits<<32 | idx), combined with max.
//   - zero-initialized .bss g_best IS the identity (no init pass)
//   - max of complement == min (d2, idx) => first-index tie-break
//   - probe seed ~(probe_d2<<32 | 0xFFFFFFFF) is provably below the true
//     winner's key (true d2 <= probe d2; real idx < 0xFFFFFFFF): filters only.
//   - finalize resets g_best/g_done to 0 => graph-replay deterministic.
//
// Candidate table: receiver r's box [r-UB, r+UB]^3 (UB = exact distance to a
// real sampled point) covers r's true NN. Cells with >KCAP receivers get
// sentinel 255 => brute-force all B for points there. Unconditionally correct.
// ============================================================================

#define GC       16
#define CELLS    (GC * GC * GC)        // 4096
#define MAXB     128
#define GRID     152
#define THREADS  1024
#define KCAP     8                     // candidate list slots per cell
#define PROBE_N  256                   // sample points for UB probe

__device__ unsigned long long g_best[MAXB];   // complemented keys; 0 = identity
__device__ unsigned int       g_done;         // zero-init; self-resetting

__device__ __forceinline__ int cell_of(float x) {
    int c = __float2int_rd(x * (float)GC);
    c = c < 0 ? 0 : c;
    return c > GC - 1 ? GC - 1 : c;
}

// ---------------------------------------------------------------------------
__global__ void __launch_bounds__(THREADS, 1)
fused_kernel(const float* __restrict__ pts, const float* __restrict__ recv,
             float* __restrict__ out, int L, int B)
{
    const int tid  = threadIdx.x;
    const int lane = tid & 31;
    const int wid  = tid >> 5;
    const int bid  = blockIdx.x;

    __shared__ float srx[MAXB], sry[MAXB], srz[MAXB];
    __shared__ float s_ub[MAXB];                       // probe min d2 per recv
    __shared__ unsigned long long s_best[MAXB];        // block-local keys
    __shared__ unsigned char s_list[CELLS * KCAP];     // 32 KB
    __shared__ unsigned char s_cnt[CELLS];             // 4 KB (255 = overflow)
    __shared__ __align__(16) float s_tile[2][3 * THREADS];  // 24 KB (AoS tiles)

    // ---- stage receivers ----
    if (tid < B) {
        srx[tid] = recv[3 * tid + 0];
        sry[tid] = recv[3 * tid + 1];
        srz[tid] = recv[3 * tid + 2];
    }

    // ---- stage probe samples AoS into s_tile[0] (768 floats) ----
    const int n = (L < PROBE_N) ? L : PROBE_N;
    if (tid < PROBE_N * 3)
        s_tile[0][tid] = (tid < n * 3) ? pts[tid] : 1.0e30f;
    __syncthreads();

    // ---- UB probe: warp wid owns receivers [4*wid, 4*wid+4) ----
    {
        const int rbase = wid * 4;
        float rx[4], ry[4], rz[4], bd[4];
#pragma unroll
        for (int k = 0; k < 4; ++k) {
            int rb = rbase + k;
            rx[k] = (rb < B) ? srx[rb] : 0.f;
            ry[k] = (rb < B) ? sry[rb] : 0.f;
            rz[k] = (rb < B) ? srz[rb] : 0.f;
            bd[k] = 3.4e38f;
        }
#pragma unroll
        for (int j = 0; j < PROBE_N / 32; ++j) {
            int i = lane + 32 * j;
            float px = s_tile[0][3 * i + 0];   // stride-3: conflict-free
            float py = s_tile[0][3 * i + 1];
            float pz = s_tile[0][3 * i + 2];
#pragma unroll
            for (int k = 0; k < 4; ++k) {
                float dx = px - rx[k];
                float dy = py - ry[k];
                float dz = pz - rz[k];
                float d2 = dx * dx + dy * dy + dz * dz;
                bd[k] = fminf(bd[k], d2);
            }
        }
#pragma unroll
        for (int k = 0; k < 4; ++k) {
#pragma unroll
            for (int m = 16; m > 0; m >>= 1)
                bd[k] = fminf(bd[k], __shfl_xor_sync(0xffffffffu, bd[k], m));
            if (lane == 0 && (rbase + k) < B) {
                s_ub[rbase + k] = bd[k];
                // seed: <= true winner's key (d2 >= true d2, idx field maximal)
                s_best[rbase + k] =
                    ~((((unsigned long long)__float_as_uint(bd[k])) << 32) |
                      0xFFFFFFFFull);
            }
        }
    }
    __syncthreads();

    // ---- zero cnt32 (reuses s_tile storage: 16 KB of the 24 KB) ----
    unsigned int* cnt32 = reinterpret_cast<unsigned int*>(&s_tile[0][0]);
#pragma unroll
    for (int j = 0; j < CELLS / THREADS; ++j) cnt32[tid + j * THREADS] = 0u;
    __syncthreads();

    // ---- build candidate lists (receiver-major, smem atomics) ----
    if (tid < B) {
        float ub = sqrtf(s_ub[tid]) * 1.0001f + 1e-7f;   // ulp guard
        float rx = srx[tid], ry = sry[tid], rz = srz[tid];
        int lx = cell_of(rx - ub), hx = cell_of(rx + ub);
        int ly = cell_of(ry - ub), hy = cell_of(ry + ub);
        int lz = cell_of(rz - ub), hz = cell_of(rz + ub);
        for (int zz = lz; zz <= hz; ++zz)
            for (int yy = ly; yy <= hy; ++yy)
                for (int xx = lx; xx <= hx; ++xx) {
                    int c = (zz * GC + yy) * GC + xx;
                    unsigned int pos = atomicAdd(&cnt32[c], 1u);
                    if (pos < KCAP) s_list[c * KCAP + pos] = (unsigned char)tid;
                }
    }
    __syncthreads();

    // ---- compact counts to u8 with overflow sentinel ----
#pragma unroll
    for (int j = 0; j < CELLS / THREADS; ++j) {
        int c = tid + j * THREADS;
        unsigned int v = cnt32[c];
        s_cnt[c] = (v > KCAP) ? (unsigned char)255 : (unsigned char)v;
    }
    __syncthreads();

    // ---- streaming pass: double-buffered AoS tiles, 1 barrier/tile ----
    const int nTiles = (L + THREADS - 1) / THREADS;
    const int L3 = L * 3;

    // prologue: stage first tile into buf 0
    if (bid < nTiles) {
        int base3 = bid * (3 * THREADS);
        if (base3 + 3 * THREADS <= L3) {
            if (tid < 768)
                reinterpret_cast<float4*>(&s_tile[0][0])[tid] =
                    reinterpret_cast<const float4*>(pts + base3)[tid];
        } else {
#pragma unroll
            for (int j = 0; j < 3; ++j) {
                int e = tid + j * THREADS;
                int ge = base3 + e;
                s_tile[0][e] = (ge < L3) ? pts[ge] : 2.0f;  // pad out of domain
            }
        }
    }
    __syncthreads();

    int buf = 0;
    for (int tile = bid; tile < nTiles; tile += GRID) {
        const int nxt = tile + GRID;
        float4 pf;
        float f0 = 0.f, f1 = 0.f, f2 = 0.f;
        bool nfull = false;
        if (nxt < nTiles) {                          // register prefetch
            int base3 = nxt * (3 * THREADS);
            nfull = (base3 + 3 * THREADS) <= L3;
            if (nfull) {
                if (tid < 768)
                    pf = reinterpret_cast<const float4*>(pts + base3)[tid];
            } else {
                int g0 = base3 + tid;
                int g1 = g0 + THREADS;
                int g2 = g1 + THREADS;
                f0 = (g0 < L3) ? pts[g0] : 2.0f;
                f1 = (g1 < L3) ? pts[g1] : 2.0f;
                f2 = (g2 < L3) ? pts[g2] : 2.0f;
            }
        }

        // process current tile (AoS reads, stride-3 => conflict-free)
        const int p = tile * THREADS + tid;
        if (p < L) {
            float x = s_tile[buf][3 * tid + 0];
            float y = s_tile[buf][3 * tid + 1];
            float z = s_tile[buf][3 * tid + 2];
            *reinterpret_cast<float4*>(out + 4 * (size_t)p) =
                make_float4(x, y, z, 0.0f);          // coalesced float4 store

            int c = (cell_of(z) * GC + cell_of(y)) * GC + cell_of(x);
            unsigned int cn = s_cnt[c];
            if (cn) {
                int lim  = (cn == 255u) ? B : (int)cn;
                bool all = (cn == 255u);
                for (int k = 0; k < lim; ++k) {
                    int r = all ? k : (int)s_list[c * KCAP + k];
                    float dx = x - srx[r];
                    float dy = y - sry[r];
                    float dz = z - srz[r];
                    float d2 = dx * dx + dy * dy + dz * dz;
                    unsigned long long key =
                        ~((((unsigned long long)__float_as_uint(d2)) << 32) |
                          (unsigned long long)(unsigned int)p);
                    // LDS guard block-coherent; smem atomic authoritative
                    if (key > s_best[r]) atomicMax(&s_best[r], key);
                }
            }
        }

        // store prefetched tile into other buffer
        if (nxt < nTiles) {
            if (nfull) {
                if (tid < 768)
                    reinterpret_cast<float4*>(&s_tile[buf ^ 1][0])[tid] = pf;
            } else {
                s_tile[buf ^ 1][tid + 0 * THREADS] = f0;
                s_tile[buf ^ 1][tid + 1 * THREADS] = f1;
                s_tile[buf ^ 1][tid + 2 * THREADS] = f2;
            }
        }
        buf ^= 1;
        __syncthreads();
    }
    __syncthreads();   // all smem atomics visible (also for zero-tile blocks)

    // ---- one global merge per block (<=128 atomics) ----
    if (tid < B) atomicMax(&g_best[tid], s_best[tid]);

    // ---- last-finishing block finalizes ----
    __threadfence();
    __syncthreads();
    __shared__ bool is_last;
    if (tid == 0) is_last = (atomicAdd(&g_done, 1u) == GRID - 1);
    __syncthreads();
    if (!is_last) return;

    if (tid < B) {
        // authoritative read (atomicMax with identity 0 leaves value intact)
        unsigned long long key = atomicMax(&g_best[tid], 0ull);
        unsigned int idx = ~((unsigned int)(key & 0xffffffffull));
        float* cp = out + 4 * (size_t)L;
        cp[3 * tid + 0] = pts[3 * idx + 0];
        cp[3 * tid + 1] = pts[3 * idx + 1];
        cp[3 * tid + 2] = pts[3 * idx + 2];
        out[4 * (size_t)L + 3 * B + tid] = (float)idx;   // min_index as float
        out[4 * (size_t)idx + 3] = 1.0f;                 // one-hot scatter
        g_best[tid] = 0ull;                              // reset for next replay
    }
    if (tid == 0) {
        if (B > 1) out[3] = 1.0f;        // reference quirk: index 0 also set
        g_done = 0u;                     // reset for next replay
    }
}

// ---------------------------------------------------------------------------
extern "C" void kernel_launch(void* const* d_in, const int* in_sizes, int n_in,
                              void* d_out, int out_size)
{
    const float* pts  = (const float*)d_in[0];   // mesh_3D flattened [L,3]
    const float* recv = (const float*)d_in[1];   // receiver_pos [B,3]
    float* out = (float*)d_out;

    int L = in_sizes[0] / 3;   // 1,000,000
    int B = in_sizes[1] / 3;   // 128

    fused_kernel<<<GRID, THREADS>>>(pts, recv, out, L, B);
}